// round 11
// baseline (speedup 1.0000x reference)
#include <cuda_runtime.h>
#include <cuda_bf16.h>
#include <cstdint>

// ---------------- problem constants ----------------
#define NEXP   16
#define NE     1024
#define ED     2048
#define NT     8192
#define KSEL   1024

// output layout (floats, concatenated tuple)
#define OFF_H    0
#define OFF_IDX  16777216
#define OFF_W    (OFF_IDX + 16384)
#define OFF_FAN  (OFF_W + 16384)
#define OFF_CUT  (OFF_FAN + 8192)

// ---------------- scratch (device globals; no cudaMalloc allowed) ----------
__device__ float g_logits[NT * NEXP];
__device__ float g_weights[NT * NEXP];
__device__ int   g_selidx[NEXP * KSEL];

__device__ __nv_bfloat16 g_xhi[(size_t)NT * NE];
__device__ __nv_bfloat16 g_xlo[(size_t)NT * NE];
__device__ __nv_bfloat16 g_w1hi[(size_t)NEXP * ED * NE];
__device__ __nv_bfloat16 g_w1lo[(size_t)NEXP * ED * NE];
__device__ __nv_bfloat16 g_w2hi[(size_t)NEXP * NE * ED];
__device__ __nv_bfloat16 g_w2lo[(size_t)NEXP * NE * ED];
__device__ __nv_bfloat16 g_hhi[(size_t)NEXP * KSEL * ED];
__device__ __nv_bfloat16 g_hlo[(size_t)NEXP * KSEL * ED];

// ---------------- PTX helpers (all baseline sm_80-class: valid compute_103) -
__device__ __forceinline__ uint32_t smem_u32(const void* p) {
    uint32_t a;
    asm("{ .reg .u64 t; cvta.to.shared.u64 t, %1; cvt.u32.u64 %0, t; }"
        : "=r"(a) : "l"(p));
    return a;
}

#define CP_ASYNC16(dst, src) \
    asm volatile("cp.async.cg.shared.global [%0], [%1], 16;" \
        :: "r"((uint32_t)(dst)), "l"((const void*)(src)) : "memory")
#define CP_COMMIT() asm volatile("cp.async.commit_group;" ::: "memory")
#define CP_WAIT1()  asm volatile("cp.async.wait_group 1;" ::: "memory")
#define CP_WAIT0()  asm volatile("cp.async.wait_group 0;" ::: "memory")

__device__ __forceinline__ void ldsm4(uint32_t& r0, uint32_t& r1,
                                      uint32_t& r2, uint32_t& r3, uint32_t addr) {
    asm volatile("ldmatrix.sync.aligned.m8n8.x4.shared.b16 {%0,%1,%2,%3}, [%4];"
        : "=r"(r0), "=r"(r1), "=r"(r2), "=r"(r3) : "r"(addr));
}

__device__ __forceinline__ void mma16816(float* d, const uint32_t* a, const uint32_t* b) {
    asm volatile(
        "mma.sync.aligned.m16n8k16.row.col.f32.bf16.bf16.f32 "
        "{%0,%1,%2,%3}, {%4,%5,%6,%7}, {%8,%9}, {%0,%1,%2,%3};"
        : "+f"(d[0]), "+f"(d[1]), "+f"(d[2]), "+f"(d[3])
        : "r"(a[0]), "r"(a[1]), "r"(a[2]), "r"(a[3]), "r"(b[0]), "r"(b[1]));
}

// ---------------- kernel 1: router logits (stride-4 ILP fp32 order) -------
// EXACT reference order (verified round 8). DO NOT CHANGE the chain.
// Round 11: smem rows padded to stride 1028 (== 4 mod 32) to kill the
// 8-way (x) / 4-way (w) bank conflicts of stride 1024.
#define XPAD 1028
extern "C" __global__ void router_seq_kernel(const float* __restrict__ x,
                                             const float* __restrict__ rw,
                                             float* __restrict__ out) {
    extern __shared__ float sm[];
    float* xs  = sm;                       // 8 rows * XPAD
    float* rws = sm + 8 * XPAD;            // 16 rows * XPAD
    float* lg  = sm + 24 * XPAD;           // 8*16

    const int tid = threadIdx.x;
    const int t0 = blockIdx.x * 8;

    if (tid < 8) out[OFF_FAN + t0 + tid] = 0.0f;

    // stage x rows and router_w with padded row stride (16B-aligned rows)
    for (int i = tid; i < 8 * (NE / 4); i += 128) {
        const int row = i >> 8, c4 = i & 255;
        *(float4*)(xs + row * XPAD + c4 * 4) =
            ((const float4*)(x + ((size_t)(t0 + row)) * NE))[c4];
    }
    for (int i = tid; i < NEXP * (NE / 4); i += 128) {
        const int row = i >> 8, c4 = i & 255;
        *(float4*)(rws + row * XPAD + c4 * 4) =
            ((const float4*)(rw + (size_t)row * NE))[c4];
    }
    __syncthreads();

    const int t = tid & 7;
    const int e = tid >> 3;
    {
        const float* xr = xs + t * XPAD;
        const float* wr = rws + e * XPAD;
        float c0 = 0.0f, c1 = 0.0f, c2 = 0.0f, c3 = 0.0f;
#pragma unroll 8
        for (int k = 0; k < NE; k += 4) {
            c0 = fmaf(xr[k + 0], wr[k + 0], c0);
            c1 = fmaf(xr[k + 1], wr[k + 1], c1);
            c2 = fmaf(xr[k + 2], wr[k + 2], c2);
            c3 = fmaf(xr[k + 3], wr[k + 3], c3);
        }
        lg[t * NEXP + e] = (c0 + c1) + (c2 + c3);
    }
    __syncthreads();

    if (tid < 8) {
        const float* row = lg + tid * NEXP;
        float m = row[0];
#pragma unroll
        for (int j = 1; j < NEXP; j++) m = fmaxf(m, row[j]);
        float ex[NEXP], s = 0.0f;
#pragma unroll
        for (int j = 0; j < NEXP; j++) { ex[j] = expf(row[j] - m); s += ex[j]; }
        const float inv = 1.0f / s;
        const int tok = t0 + tid;
#pragma unroll
        for (int j = 0; j < NEXP; j++) {
            g_logits[tok * NEXP + j]  = row[j];
            g_weights[tok * NEXP + j] = ex[j] * inv;
        }
    }
}
#define ROUTER_SMEM ((24 * XPAD + 128) * 4)

// ---------------- kernel 2: exact per-expert top-k via bitonic sort --------
extern "C" __global__ void topk_kernel(float* __restrict__ out) {
    extern __shared__ unsigned long long key[];
    const int e = blockIdx.x;
    const int tid = threadIdx.x;

    for (int i = tid; i < NT; i += 1024) {
        const unsigned b = __float_as_uint(g_logits[i * NEXP + e]);
        const unsigned m = b ^ ((b & 0x80000000u) ? 0xFFFFFFFFu : 0x80000000u);
        key[i] = ((unsigned long long)(~m) << 32) | (unsigned)i;
    }
    __syncthreads();

    for (unsigned k = 2; k <= NT; k <<= 1) {
        for (unsigned j = k >> 1; j > 0; j >>= 1) {
            for (unsigned i = tid; i < NT; i += 1024) {
                const unsigned ixj = i ^ j;
                if (ixj > i) {
                    const bool up = ((i & k) == 0);
                    const unsigned long long a = key[i], b = key[ixj];
                    if ((a > b) == up) { key[i] = b; key[ixj] = a; }
                }
            }
            __syncthreads();
        }
    }

    if (tid < KSEL) {
        const unsigned long long kk = key[tid];
        const unsigned idx = (unsigned)(kk & 0xFFFFFFFFu);
        const unsigned m = ~((unsigned)(kk >> 32));
        const unsigned b = (m & 0x80000000u) ? (m ^ 0x80000000u) : ~m;
        const float val = __uint_as_float(b);

        out[OFF_IDX + e * KSEL + tid] = (float)idx;
        out[OFF_W   + e * KSEL + tid] = g_weights[idx * NEXP + e];
        g_selidx[e * KSEL + tid] = (int)idx;
        atomicAdd(&out[OFF_FAN + idx], 1.0f);
        if (tid == KSEL - 1) out[OFF_CUT + e] = val;
    }
}

// ---------------- kernel 3: fp32 -> bf16 hi/lo split -----------------------
extern "C" __global__ void split_kernel(const float* __restrict__ in,
                                        __nv_bfloat16* __restrict__ hi,
                                        __nv_bfloat16* __restrict__ lo, int n4) {
    const int i = blockIdx.x * blockDim.x + threadIdx.x;
    if (i >= n4) return;
    const float4 v = ((const float4*)in)[i];
    union { __nv_bfloat16 b[4]; uint2 u; } ph, pl;
    float vv[4] = {v.x, v.y, v.z, v.w};
#pragma unroll
    for (int j = 0; j < 4; j++) {
        __nv_bfloat16 h = __float2bfloat16(vv[j]);
        ph.b[j] = h;
        pl.b[j] = __float2bfloat16(vv[j] - __bfloat162float(h));
    }
    ((uint2*)hi)[i] = ph.u;
    ((uint2*)lo)[i] = pl.u;
}

// ---------------- kernels 4/5: mma.sync bf16x3 GEMM ------------------------
// C[1024 x NDIM] = A[1024 x KREAL] @ B[NDIM x KREAL]^T per expert (TN).
// Virtual K' = 3*KREAL; chunks of 64: A planes [hi,hi,lo], B planes [hi,lo,hi].
// CTA tile 128x128, 8 warps of 32(m)x64(n); cp.async double buffer;
// smem rows 128B data padded to 144B (conflict-free ldmatrix phases).
#define ROWB 144
#define OPER_B (128 * ROWB)          // 18432 per operand per stage
#define STG_B  (2 * OPER_B)          // 36864 per stage
#define SMEM_MMA (2 * STG_B + 512)

template <int KREAL, int NDIM, int GATHER, int RELU2OUT>
__global__ void __launch_bounds__(256, 2)
mma_gemm(const __nv_bfloat16* __restrict__ Ahi, const __nv_bfloat16* __restrict__ Alo,
         const __nv_bfloat16* __restrict__ Bhi, const __nv_bfloat16* __restrict__ Blo,
         float* __restrict__ Cf,
         __nv_bfloat16* __restrict__ Chi, __nv_bfloat16* __restrict__ Clo) {
    extern __shared__ char smem[];
    const uint32_t sb = smem_u32(smem);
    const int tid = threadIdx.x, wid = tid >> 5, lane = tid & 31;
    const int m0 = blockIdx.x * 128, n0 = blockIdx.y * 128, e = blockIdx.z;

    int* sidx = (int*)(smem + 2 * STG_B);
    if (GATHER && tid < 128) sidx[tid] = g_selidx[e * KSEL + m0 + tid];
    __syncthreads();

    // global->smem: per operand 128 rows x 128B; 2 threads/row x 4 x 16B.
    const int r = tid >> 1, sg = tid & 1;
    const size_t arow = GATHER ? (size_t)sidx[r] : ((size_t)e * 1024 + m0 + r);
    const size_t brow = (size_t)e * NDIM + n0 + r;
    const uint32_t soff = (uint32_t)r * ROWB + sg * 64;

    constexpr int KC = KREAL / 64;
    constexpr int NCH = 3 * KC;

    auto issue = [&](int c, int st) {
        const int b = c / KC;
        const int kk = (c - b * KC) * 64;
        const __nv_bfloat16* Ap = (b == 2) ? Alo : Ahi;
        const __nv_bfloat16* Bp = (b == 1) ? Blo : Bhi;
        const uint32_t base = sb + st * STG_B;
        const __nv_bfloat16* as = Ap + arow * KREAL + kk + sg * 32;
        const __nv_bfloat16* bs = Bp + brow * KREAL + kk + sg * 32;
#pragma unroll
        for (int j = 0; j < 4; j++) {
            CP_ASYNC16(base + soff + j * 16, as + j * 8);
            CP_ASYNC16(base + OPER_B + soff + j * 16, bs + j * 8);
        }
        CP_COMMIT();
    };

    // warp tile: 32(m) x 64(n)
    const int wm = wid & 3, wn = wid >> 2;
    const uint32_t a_l = (uint32_t)(wm * 32 + (lane & 15)) * ROWB + (lane >> 4) * 16;
    const uint32_t b_l = (uint32_t)(wn * 64 + (lane & 7) + ((lane >> 4) & 1) * 8) * ROWB
                         + ((lane >> 3) & 1) * 16;

    float d[2][8][4] = {};

    issue(0, 0);
    for (int c = 0; c < NCH; c++) {
        const int st = c & 1;
        if (c + 1 < NCH) { issue(c + 1, st ^ 1); CP_WAIT1(); }
        else             { CP_WAIT0(); }
        __syncthreads();

        const uint32_t ab = sb + st * STG_B;
        const uint32_t bb = ab + OPER_B;
#pragma unroll
        for (int ks = 0; ks < 4; ks++) {
            uint32_t a[2][4], bf[8][2];
#pragma unroll
            for (int mi = 0; mi < 2; mi++)
                ldsm4(a[mi][0], a[mi][1], a[mi][2], a[mi][3],
                      ab + a_l + mi * 16 * ROWB + ks * 32);
#pragma unroll
            for (int nb = 0; nb < 4; nb++) {
                uint32_t t0, t1, t2, t3;
                ldsm4(t0, t1, t2, t3, bb + b_l + nb * 16 * ROWB + ks * 32);
                bf[2 * nb][0] = t0; bf[2 * nb][1] = t1;
                bf[2 * nb + 1][0] = t2; bf[2 * nb + 1][1] = t3;
            }
#pragma unroll
            for (int mi = 0; mi < 2; mi++)
#pragma unroll
                for (int ni = 0; ni < 8; ni++)
                    mma16816(d[mi][ni], a[mi], bf[ni]);
        }
        __syncthreads();
    }

    // epilogue
    const int mb = m0 + wm * 32;
    const int nb0 = n0 + wn * 64;
#pragma unroll
    for (int mi = 0; mi < 2; mi++)
#pragma unroll
        for (int half = 0; half < 2; half++) {
            const int m = mb + mi * 16 + (lane >> 2) + half * 8;
            const size_t rowoff = ((size_t)e * 1024 + m) * NDIM;
#pragma unroll
            for (int ni = 0; ni < 8; ni++) {
                const int n = nb0 + ni * 8 + (lane & 3) * 2;
                float v0 = d[mi][ni][2 * half + 0];
                float v1 = d[mi][ni][2 * half + 1];
                if (RELU2OUT) {
                    v0 = fmaxf(v0, 0.0f); v0 *= v0;
                    v1 = fmaxf(v1, 0.0f); v1 *= v1;
                    __nv_bfloat16 h0 = __float2bfloat16(v0);
                    __nv_bfloat16 h1 = __float2bfloat16(v1);
                    __nv_bfloat16 l0 = __float2bfloat16(v0 - __bfloat162float(h0));
                    __nv_bfloat16 l1 = __float2bfloat16(v1 - __bfloat162float(h1));
                    __nv_bfloat162 hp; hp.x = h0; hp.y = h1;
                    __nv_bfloat162 lp; lp.x = l0; lp.y = l1;
                    *(__nv_bfloat162*)(Chi + rowoff + n) = hp;
                    *(__nv_bfloat162*)(Clo + rowoff + n) = lp;
                } else {
                    float2 s2; s2.x = v0; s2.y = v1;
                    *(float2*)(Cf + rowoff + n) = s2;
                }
            }
        }
}

// ---------------- launch ----------------
extern "C" void kernel_launch(void* const* d_in, const int* in_sizes, int n_in,
                              void* d_out, int out_size) {
    const float* x  = (const float*)d_in[0];
    const float* rw = (const float*)d_in[1];
    const float* w1 = (const float*)d_in[2];
    const float* w2 = (const float*)d_in[3];
    float* out = (float*)d_out;

    cudaFuncSetAttribute(router_seq_kernel,
                         cudaFuncAttributeMaxDynamicSharedMemorySize, 101376);
    cudaFuncSetAttribute(topk_kernel,
                         cudaFuncAttributeMaxDynamicSharedMemorySize, 65536);
    cudaFuncSetAttribute(mma_gemm<NE, ED, 1, 1>,
                         cudaFuncAttributeMaxDynamicSharedMemorySize, SMEM_MMA);
    cudaFuncSetAttribute(mma_gemm<ED, NE, 0, 0>,
                         cudaFuncAttributeMaxDynamicSharedMemorySize, SMEM_MMA);

    __nv_bfloat16 *xhi, *xlo, *w1hi, *w1lo, *w2hi, *w2lo, *hhi, *hlo;
    cudaGetSymbolAddress((void**)&xhi,  g_xhi);
    cudaGetSymbolAddress((void**)&xlo,  g_xlo);
    cudaGetSymbolAddress((void**)&w1hi, g_w1hi);
    cudaGetSymbolAddress((void**)&w1lo, g_w1lo);
    cudaGetSymbolAddress((void**)&w2hi, g_w2hi);
    cudaGetSymbolAddress((void**)&w2lo, g_w2lo);
    cudaGetSymbolAddress((void**)&hhi,  g_hhi);
    cudaGetSymbolAddress((void**)&hlo,  g_hlo);

    // 1) bf16 hi/lo splits
    split_kernel<<<(NT * NE / 4 + 255) / 256, 256>>>(x, xhi, xlo, NT * NE / 4);
    split_kernel<<<(NEXP * ED * NE / 4 + 255) / 256, 256>>>(w1, w1hi, w1lo, NEXP * ED * NE / 4);
    split_kernel<<<(NEXP * NE * ED / 4 + 255) / 256, 256>>>(w2, w2hi, w2lo, NEXP * NE * ED / 4);

    // 2) router logits (EXACT reference fp32 order) + softmax + fanout zero
    router_seq_kernel<<<NT / 8, 128, ROUTER_SMEM>>>(x, rw, out);

    // 3) exact top-1024 per expert
    topk_kernel<<<NEXP, 1024, 65536>>>(out);

    // 4) h = relu(x_sel @ w1^T)^2 -> bf16 hi/lo planes (mma.sync bf16x3)
    {
        dim3 grid(KSEL / 128, ED / 128, NEXP);
        mma_gemm<NE, ED, 1, 1><<<grid, 256, SMEM_MMA>>>(
            xhi, xlo, w1hi, w1lo, nullptr, hhi, hlo);
    }
    // 5) h_flat = h @ w2^T -> d_out (mma.sync bf16x3)
    {
        dim3 grid(KSEL / 128, NE / 128, NEXP);
        mma_gemm<ED, NE, 0, 0><<<grid, 256, SMEM_MMA>>>(
            hhi, hlo, w2hi, w2lo, out + OFF_H, nullptr, nullptr);
    }
}

// round 12
// speedup vs baseline: 1.2257x; 1.2257x over previous
#include <cuda_runtime.h>
#include <cuda_bf16.h>
#include <cstdint>

// ---------------- problem constants ----------------
#define NEXP   16
#define NE     1024
#define ED     2048
#define NT     8192
#define KSEL   1024

// output layout (floats, concatenated tuple)
#define OFF_H    0
#define OFF_IDX  16777216
#define OFF_W    (OFF_IDX + 16384)
#define OFF_FAN  (OFF_W + 16384)
#define OFF_CUT  (OFF_FAN + 8192)

// ---------------- scratch (device globals; no cudaMalloc allowed) ----------
__device__ float g_logits[NT * NEXP];
__device__ float g_weights[NT * NEXP];
__device__ int   g_selidx[NEXP * KSEL];

__device__ __nv_bfloat16 g_xhi[(size_t)NT * NE];
__device__ __nv_bfloat16 g_xlo[(size_t)NT * NE];
__device__ __nv_bfloat16 g_w1hi[(size_t)NEXP * ED * NE];
__device__ __nv_bfloat16 g_w1lo[(size_t)NEXP * ED * NE];
__device__ __nv_bfloat16 g_w2hi[(size_t)NEXP * NE * ED];
__device__ __nv_bfloat16 g_w2lo[(size_t)NEXP * NE * ED];
__device__ __nv_bfloat16 g_hhi[(size_t)NEXP * KSEL * ED];
__device__ __nv_bfloat16 g_hlo[(size_t)NEXP * KSEL * ED];

// ---------------- PTX helpers (all baseline sm_80-class: valid compute_103) -
__device__ __forceinline__ uint32_t smem_u32(const void* p) {
    uint32_t a;
    asm("{ .reg .u64 t; cvta.to.shared.u64 t, %1; cvt.u32.u64 %0, t; }"
        : "=r"(a) : "l"(p));
    return a;
}

#define CP_ASYNC16(dst, src) \
    asm volatile("cp.async.cg.shared.global [%0], [%1], 16;" \
        :: "r"((uint32_t)(dst)), "l"((const void*)(src)) : "memory")
#define CP_COMMIT() asm volatile("cp.async.commit_group;" ::: "memory")
#define CP_WAIT1()  asm volatile("cp.async.wait_group 1;" ::: "memory")
#define CP_WAIT0()  asm volatile("cp.async.wait_group 0;" ::: "memory")

__device__ __forceinline__ void ldsm4(uint32_t& r0, uint32_t& r1,
                                      uint32_t& r2, uint32_t& r3, uint32_t addr) {
    asm volatile("ldmatrix.sync.aligned.m8n8.x4.shared.b16 {%0,%1,%2,%3}, [%4];"
        : "=r"(r0), "=r"(r1), "=r"(r2), "=r"(r3) : "r"(addr));
}

__device__ __forceinline__ void mma16816(float* d, const uint32_t* a, const uint32_t* b) {
    asm volatile(
        "mma.sync.aligned.m16n8k16.row.col.f32.bf16.bf16.f32 "
        "{%0,%1,%2,%3}, {%4,%5,%6,%7}, {%8,%9}, {%0,%1,%2,%3};"
        : "+f"(d[0]), "+f"(d[1]), "+f"(d[2]), "+f"(d[3])
        : "r"(a[0]), "r"(a[1]), "r"(a[2]), "r"(a[3]), "r"(b[0]), "r"(b[1]));
}

// ---------------- kernel 1: router logits (stride-4 ILP fp32 order) -------
// EXACT reference order (verified round 8). DO NOT CHANGE the chain.
// Padded smem stride 1028 (== 4 mod 32): kills 8-way/4-way bank conflicts
// (measured 187 -> 68 us in round 11).
#define XPAD 1028
extern "C" __global__ void router_seq_kernel(const float* __restrict__ x,
                                             const float* __restrict__ rw,
                                             float* __restrict__ out) {
    extern __shared__ float sm[];
    float* xs  = sm;                       // 8 rows * XPAD
    float* rws = sm + 8 * XPAD;            // 16 rows * XPAD
    float* lg  = sm + 24 * XPAD;           // 8*16

    const int tid = threadIdx.x;
    const int t0 = blockIdx.x * 8;

    if (tid < 8) out[OFF_FAN + t0 + tid] = 0.0f;

    for (int i = tid; i < 8 * (NE / 4); i += 128) {
        const int row = i >> 8, c4 = i & 255;
        *(float4*)(xs + row * XPAD + c4 * 4) =
            ((const float4*)(x + ((size_t)(t0 + row)) * NE))[c4];
    }
    for (int i = tid; i < NEXP * (NE / 4); i += 128) {
        const int row = i >> 8, c4 = i & 255;
        *(float4*)(rws + row * XPAD + c4 * 4) =
            ((const float4*)(rw + (size_t)row * NE))[c4];
    }
    __syncthreads();

    const int t = tid & 7;
    const int e = tid >> 3;
    {
        const float* xr = xs + t * XPAD;
        const float* wr = rws + e * XPAD;
        float c0 = 0.0f, c1 = 0.0f, c2 = 0.0f, c3 = 0.0f;
#pragma unroll 8
        for (int k = 0; k < NE; k += 4) {
            c0 = fmaf(xr[k + 0], wr[k + 0], c0);
            c1 = fmaf(xr[k + 1], wr[k + 1], c1);
            c2 = fmaf(xr[k + 2], wr[k + 2], c2);
            c3 = fmaf(xr[k + 3], wr[k + 3], c3);
        }
        lg[t * NEXP + e] = (c0 + c1) + (c2 + c3);
    }
    __syncthreads();

    if (tid < 8) {
        const float* row = lg + tid * NEXP;
        float m = row[0];
#pragma unroll
        for (int j = 1; j < NEXP; j++) m = fmaxf(m, row[j]);
        float ex[NEXP], s = 0.0f;
#pragma unroll
        for (int j = 0; j < NEXP; j++) { ex[j] = expf(row[j] - m); s += ex[j]; }
        const float inv = 1.0f / s;
        const int tok = t0 + tid;
#pragma unroll
        for (int j = 0; j < NEXP; j++) {
            g_logits[tok * NEXP + j]  = row[j];
            g_weights[tok * NEXP + j] = ex[j] * inv;
        }
    }
}
#define ROUTER_SMEM ((24 * XPAD + 128) * 4)

// ---------------- kernel 2: exact per-expert top-k via bitonic sort --------
extern "C" __global__ void topk_kernel(float* __restrict__ out) {
    extern __shared__ unsigned long long key[];
    const int e = blockIdx.x;
    const int tid = threadIdx.x;

    for (int i = tid; i < NT; i += 1024) {
        const unsigned b = __float_as_uint(g_logits[i * NEXP + e]);
        const unsigned m = b ^ ((b & 0x80000000u) ? 0xFFFFFFFFu : 0x80000000u);
        key[i] = ((unsigned long long)(~m) << 32) | (unsigned)i;
    }
    __syncthreads();

    for (unsigned k = 2; k <= NT; k <<= 1) {
        for (unsigned j = k >> 1; j > 0; j >>= 1) {
            for (unsigned i = tid; i < NT; i += 1024) {
                const unsigned ixj = i ^ j;
                if (ixj > i) {
                    const bool up = ((i & k) == 0);
                    const unsigned long long a = key[i], b = key[ixj];
                    if ((a > b) == up) { key[i] = b; key[ixj] = a; }
                }
            }
            __syncthreads();
        }
    }

    if (tid < KSEL) {
        const unsigned long long kk = key[tid];
        const unsigned idx = (unsigned)(kk & 0xFFFFFFFFu);
        const unsigned m = ~((unsigned)(kk >> 32));
        const unsigned b = (m & 0x80000000u) ? (m ^ 0x80000000u) : ~m;
        const float val = __uint_as_float(b);

        out[OFF_IDX + e * KSEL + tid] = (float)idx;
        out[OFF_W   + e * KSEL + tid] = g_weights[idx * NEXP + e];
        g_selidx[e * KSEL + tid] = (int)idx;
        atomicAdd(&out[OFF_FAN + idx], 1.0f);
        if (tid == KSEL - 1) out[OFF_CUT + e] = val;
    }
}

// ---------------- kernel 3: fp32 -> bf16 hi/lo split -----------------------
extern "C" __global__ void split_kernel(const float* __restrict__ in,
                                        __nv_bfloat16* __restrict__ hi,
                                        __nv_bfloat16* __restrict__ lo, int n4) {
    const int i = blockIdx.x * blockDim.x + threadIdx.x;
    if (i >= n4) return;
    const float4 v = ((const float4*)in)[i];
    union { __nv_bfloat16 b[4]; uint2 u; } ph, pl;
    float vv[4] = {v.x, v.y, v.z, v.w};
#pragma unroll
    for (int j = 0; j < 4; j++) {
        __nv_bfloat16 h = __float2bfloat16(vv[j]);
        ph.b[j] = h;
        pl.b[j] = __float2bfloat16(vv[j] - __bfloat162float(h));
    }
    ((uint2*)hi)[i] = ph.u;
    ((uint2*)lo)[i] = pl.u;
}

// ---------------- kernels 4/5: mma.sync bf16x3 GEMM ------------------------
// EXACT round-10 configuration (measured 1712 us total): CTA tile 128x128,
// 8 warps of 32(m)x64(n), k-chunk 32, cp.async double buffer, ROWB=80.
#define ROWB 80
#define OPER_B (128 * ROWB)          // 10240 per operand per stage
#define STG_B  (2 * OPER_B)          // 20480 per stage
#define SMEM_MMA (2 * STG_B + 512)

template <int KREAL, int NDIM, int GATHER, int RELU2OUT>
__global__ void __launch_bounds__(256, 2)
mma_gemm(const __nv_bfloat16* __restrict__ Ahi, const __nv_bfloat16* __restrict__ Alo,
         const __nv_bfloat16* __restrict__ Bhi, const __nv_bfloat16* __restrict__ Blo,
         float* __restrict__ Cf,
         __nv_bfloat16* __restrict__ Chi, __nv_bfloat16* __restrict__ Clo) {
    extern __shared__ char smem[];
    const uint32_t sb = smem_u32(smem);
    const int tid = threadIdx.x, wid = tid >> 5, lane = tid & 31;
    const int m0 = blockIdx.x * 128, n0 = blockIdx.y * 128, e = blockIdx.z;

    int* sidx = (int*)(smem + 2 * STG_B);
    if (GATHER && tid < 128) sidx[tid] = g_selidx[e * KSEL + m0 + tid];
    __syncthreads();

    const int r0 = tid >> 2, sg = tid & 3, r1 = r0 + 64;
    const size_t ar0 = GATHER ? (size_t)sidx[r0] : ((size_t)e * 1024 + m0 + r0);
    const size_t ar1 = GATHER ? (size_t)sidx[r1] : ((size_t)e * 1024 + m0 + r1);
    const size_t br0 = (size_t)e * NDIM + n0 + r0;
    const size_t br1 = (size_t)e * NDIM + n0 + r1;
    const uint32_t aoff0 = r0 * ROWB + sg * 16;
    const uint32_t aoff1 = r1 * ROWB + sg * 16;

    constexpr int KC = KREAL / 32;
    constexpr int NCH = 3 * KC;

    auto issue = [&](int c, int st) {
        const int b = c / KC;
        const int kk = (c - b * KC) * 32;
        const __nv_bfloat16* Ap = (b == 2) ? Alo : Ahi;
        const __nv_bfloat16* Bp = (b == 1) ? Blo : Bhi;
        const uint32_t base = sb + st * STG_B;
        CP_ASYNC16(base + aoff0, Ap + ar0 * KREAL + kk + sg * 8);
        CP_ASYNC16(base + aoff1, Ap + ar1 * KREAL + kk + sg * 8);
        CP_ASYNC16(base + OPER_B + aoff0, Bp + br0 * KREAL + kk + sg * 8);
        CP_ASYNC16(base + OPER_B + aoff1, Bp + br1 * KREAL + kk + sg * 8);
        CP_COMMIT();
    };

    // warp tile: 32(m) x 64(n)
    const int wm = wid & 3, wn = wid >> 2;
    const uint32_t a_l = (uint32_t)(wm * 32 + (lane & 15)) * ROWB + (lane >> 4) * 16;
    const uint32_t b_l = (uint32_t)(wn * 64 + (lane & 7) + ((lane >> 4) & 1) * 8) * ROWB
                         + ((lane >> 3) & 1) * 16;

    float d[2][8][4] = {};

    issue(0, 0);
    for (int c = 0; c < NCH; c++) {
        const int st = c & 1;
        if (c + 1 < NCH) { issue(c + 1, st ^ 1); CP_WAIT1(); }
        else             { CP_WAIT0(); }
        __syncthreads();

        const uint32_t ab = sb + st * STG_B;
        const uint32_t bb = ab + OPER_B;
#pragma unroll
        for (int ks = 0; ks < 2; ks++) {
            uint32_t a[2][4], bf[8][2];
#pragma unroll
            for (int mi = 0; mi < 2; mi++)
                ldsm4(a[mi][0], a[mi][1], a[mi][2], a[mi][3],
                      ab + a_l + mi * 16 * ROWB + ks * 32);
#pragma unroll
            for (int nb = 0; nb < 4; nb++) {
                uint32_t t0, t1, t2, t3;
                ldsm4(t0, t1, t2, t3, bb + b_l + nb * 16 * ROWB + ks * 32);
                bf[2 * nb][0] = t0; bf[2 * nb][1] = t1;
                bf[2 * nb + 1][0] = t2; bf[2 * nb + 1][1] = t3;
            }
#pragma unroll
            for (int mi = 0; mi < 2; mi++)
#pragma unroll
                for (int ni = 0; ni < 8; ni++)
                    mma16816(d[mi][ni], a[mi], bf[ni]);
        }
        __syncthreads();
    }

    // epilogue
    const int mb = m0 + wm * 32;
    const int nb0 = n0 + wn * 64;
#pragma unroll
    for (int mi = 0; mi < 2; mi++)
#pragma unroll
        for (int half = 0; half < 2; half++) {
            const int m = mb + mi * 16 + (lane >> 2) + half * 8;
            const size_t rowoff = ((size_t)e * 1024 + m) * NDIM;
#pragma unroll
            for (int ni = 0; ni < 8; ni++) {
                const int n = nb0 + ni * 8 + (lane & 3) * 2;
                float v0 = d[mi][ni][2 * half + 0];
                float v1 = d[mi][ni][2 * half + 1];
                if (RELU2OUT) {
                    v0 = fmaxf(v0, 0.0f); v0 *= v0;
                    v1 = fmaxf(v1, 0.0f); v1 *= v1;
                    __nv_bfloat16 h0 = __float2bfloat16(v0);
                    __nv_bfloat16 h1 = __float2bfloat16(v1);
                    __nv_bfloat16 l0 = __float2bfloat16(v0 - __bfloat162float(h0));
                    __nv_bfloat16 l1 = __float2bfloat16(v1 - __bfloat162float(h1));
                    __nv_bfloat162 hp; hp.x = h0; hp.y = h1;
                    __nv_bfloat162 lp; lp.x = l0; lp.y = l1;
                    *(__nv_bfloat162*)(Chi + rowoff + n) = hp;
                    *(__nv_bfloat162*)(Clo + rowoff + n) = lp;
                } else {
                    float2 s2; s2.x = v0; s2.y = v1;
                    *(float2*)(Cf + rowoff + n) = s2;
                }
            }
        }
}

// ---------------- launch ----------------
extern "C" void kernel_launch(void* const* d_in, const int* in_sizes, int n_in,
                              void* d_out, int out_size) {
    const float* x  = (const float*)d_in[0];
    const float* rw = (const float*)d_in[1];
    const float* w1 = (const float*)d_in[2];
    const float* w2 = (const float*)d_in[3];
    float* out = (float*)d_out;

    cudaFuncSetAttribute(router_seq_kernel,
                         cudaFuncAttributeMaxDynamicSharedMemorySize, 101376);
    cudaFuncSetAttribute(topk_kernel,
                         cudaFuncAttributeMaxDynamicSharedMemorySize, 65536);
    cudaFuncSetAttribute(mma_gemm<NE, ED, 1, 1>,
                         cudaFuncAttributeMaxDynamicSharedMemorySize, SMEM_MMA);
    cudaFuncSetAttribute(mma_gemm<ED, NE, 0, 0>,
                         cudaFuncAttributeMaxDynamicSharedMemorySize, SMEM_MMA);

    __nv_bfloat16 *xhi, *xlo, *w1hi, *w1lo, *w2hi, *w2lo, *hhi, *hlo;
    cudaGetSymbolAddress((void**)&xhi,  g_xhi);
    cudaGetSymbolAddress((void**)&xlo,  g_xlo);
    cudaGetSymbolAddress((void**)&w1hi, g_w1hi);
    cudaGetSymbolAddress((void**)&w1lo, g_w1lo);
    cudaGetSymbolAddress((void**)&w2hi, g_w2hi);
    cudaGetSymbolAddress((void**)&w2lo, g_w2lo);
    cudaGetSymbolAddress((void**)&hhi,  g_hhi);
    cudaGetSymbolAddress((void**)&hlo,  g_hlo);

    // 1) bf16 hi/lo splits
    split_kernel<<<(NT * NE / 4 + 255) / 256, 256>>>(x, xhi, xlo, NT * NE / 4);
    split_kernel<<<(NEXP * ED * NE / 4 + 255) / 256, 256>>>(w1, w1hi, w1lo, NEXP * ED * NE / 4);
    split_kernel<<<(NEXP * NE * ED / 4 + 255) / 256, 256>>>(w2, w2hi, w2lo, NEXP * NE * ED / 4);

    // 2) router logits (EXACT reference fp32 order) + softmax + fanout zero
    router_seq_kernel<<<NT / 8, 128, ROUTER_SMEM>>>(x, rw, out);

    // 3) exact top-1024 per expert
    topk_kernel<<<NEXP, 1024, 65536>>>(out);

    // 4) h = relu(x_sel @ w1^T)^2 -> bf16 hi/lo planes (mma.sync bf16x3)
    {
        dim3 grid(KSEL / 128, ED / 128, NEXP);
        mma_gemm<NE, ED, 1, 1><<<grid, 256, SMEM_MMA>>>(
            xhi, xlo, w1hi, w1lo, nullptr, hhi, hlo);
    }
    // 5) h_flat = h @ w2^T -> d_out (mma.sync bf16x3)
    {
        dim3 grid(KSEL / 128, NE / 128, NEXP);
        mma_gemm<ED, NE, 0, 0><<<grid, 256, SMEM_MMA>>>(
            hhi, hlo, w2hi, w2lo, out + OFF_H, nullptr, nullptr);
    }
}

// round 14
// speedup vs baseline: 1.3084x; 1.0675x over previous
#include <cuda_runtime.h>
#include <cuda_bf16.h>
#include <cstdint>

// ---------------- problem constants ----------------
#define NEXP   16
#define NE     1024
#define ED     2048
#define NT     8192
#define KSEL   1024

// output layout (floats, concatenated tuple)
#define OFF_H    0
#define OFF_IDX  16777216
#define OFF_W    (OFF_IDX + 16384)
#define OFF_FAN  (OFF_W + 16384)
#define OFF_CUT  (OFF_FAN + 8192)

// ---------------- scratch (device globals; no cudaMalloc allowed) ----------
__device__ float g_logits[NT * NEXP];
__device__ float g_weights[NT * NEXP];
__device__ int   g_selidx[NEXP * KSEL];

__device__ __nv_bfloat16 g_xhi[(size_t)NT * NE];
__device__ __nv_bfloat16 g_xlo[(size_t)NT * NE];
__device__ __nv_bfloat16 g_w1hi[(size_t)NEXP * ED * NE];
__device__ __nv_bfloat16 g_w1lo[(size_t)NEXP * ED * NE];
__device__ __nv_bfloat16 g_w2hi[(size_t)NEXP * NE * ED];
__device__ __nv_bfloat16 g_w2lo[(size_t)NEXP * NE * ED];
__device__ __nv_bfloat16 g_hhi[(size_t)NEXP * KSEL * ED];
__device__ __nv_bfloat16 g_hlo[(size_t)NEXP * KSEL * ED];

// ---------------- PTX helpers (all baseline sm_80-class: valid compute_103) -
__device__ __forceinline__ uint32_t smem_u32(const void* p) {
    uint32_t a;
    asm("{ .reg .u64 t; cvta.to.shared.u64 t, %1; cvt.u32.u64 %0, t; }"
        : "=r"(a) : "l"(p));
    return a;
}

#define CP_ASYNC16(dst, src) \
    asm volatile("cp.async.cg.shared.global [%0], [%1], 16;" \
        :: "r"((uint32_t)(dst)), "l"((const void*)(src)) : "memory")
#define CP_COMMIT() asm volatile("cp.async.commit_group;" ::: "memory")
#define CP_WAIT1()  asm volatile("cp.async.wait_group 1;" ::: "memory")
#define CP_WAIT0()  asm volatile("cp.async.wait_group 0;" ::: "memory")

__device__ __forceinline__ void ldsm4(uint32_t& r0, uint32_t& r1,
                                      uint32_t& r2, uint32_t& r3, uint32_t addr) {
    asm volatile("ldmatrix.sync.aligned.m8n8.x4.shared.b16 {%0,%1,%2,%3}, [%4];"
        : "=r"(r0), "=r"(r1), "=r"(r2), "=r"(r3) : "r"(addr));
}

__device__ __forceinline__ void mma16816(float* d, const uint32_t* a, const uint32_t* b) {
    asm volatile(
        "mma.sync.aligned.m16n8k16.row.col.f32.bf16.bf16.f32 "
        "{%0,%1,%2,%3}, {%4,%5,%6,%7}, {%8,%9}, {%0,%1,%2,%3};"
        : "+f"(d[0]), "+f"(d[1]), "+f"(d[2]), "+f"(d[3])
        : "r"(a[0]), "r"(a[1]), "r"(a[2]), "r"(a[3]), "r"(b[0]), "r"(b[1]));
}

// ---------------- kernel 1: router logits (stride-4 ILP fp32 order) -------
// EXACT reference order (verified round 8). DO NOT CHANGE the chain.
// Padded smem stride 1028 (== 4 mod 32): kills bank conflicts (meas. 187->67us).
#define XPAD 1028
extern "C" __global__ void router_seq_kernel(const float* __restrict__ x,
                                             const float* __restrict__ rw,
                                             float* __restrict__ out) {
    extern __shared__ float sm[];
    float* xs  = sm;                       // 8 rows * XPAD
    float* rws = sm + 8 * XPAD;            // 16 rows * XPAD
    float* lg  = sm + 24 * XPAD;           // 8*16

    const int tid = threadIdx.x;
    const int t0 = blockIdx.x * 8;

    if (tid < 8) out[OFF_FAN + t0 + tid] = 0.0f;

    for (int i = tid; i < 8 * (NE / 4); i += 128) {
        const int row = i >> 8, c4 = i & 255;
        *(float4*)(xs + row * XPAD + c4 * 4) =
            ((const float4*)(x + ((size_t)(t0 + row)) * NE))[c4];
    }
    for (int i = tid; i < NEXP * (NE / 4); i += 128) {
        const int row = i >> 8, c4 = i & 255;
        *(float4*)(rws + row * XPAD + c4 * 4) =
            ((const float4*)(rw + (size_t)row * NE))[c4];
    }
    __syncthreads();

    const int t = tid & 7;
    const int e = tid >> 3;
    {
        const float* xr = xs + t * XPAD;
        const float* wr = rws + e * XPAD;
        float c0 = 0.0f, c1 = 0.0f, c2 = 0.0f, c3 = 0.0f;
#pragma unroll 8
        for (int k = 0; k < NE; k += 4) {
            c0 = fmaf(xr[k + 0], wr[k + 0], c0);
            c1 = fmaf(xr[k + 1], wr[k + 1], c1);
            c2 = fmaf(xr[k + 2], wr[k + 2], c2);
            c3 = fmaf(xr[k + 3], wr[k + 3], c3);
        }
        lg[t * NEXP + e] = (c0 + c1) + (c2 + c3);
    }
    __syncthreads();

    if (tid < 8) {
        const float* row = lg + tid * NEXP;
        float m = row[0];
#pragma unroll
        for (int j = 1; j < NEXP; j++) m = fmaxf(m, row[j]);
        float ex[NEXP], s = 0.0f;
#pragma unroll
        for (int j = 0; j < NEXP; j++) { ex[j] = expf(row[j] - m); s += ex[j]; }
        const float inv = 1.0f / s;
        const int tok = t0 + tid;
#pragma unroll
        for (int j = 0; j < NEXP; j++) {
            g_logits[tok * NEXP + j]  = row[j];
            g_weights[tok * NEXP + j] = ex[j] * inv;
        }
    }
}
#define ROUTER_SMEM ((24 * XPAD + 128) * 4)

// ---------------- kernel 2: exact per-expert top-k via bitonic sort --------
extern "C" __global__ void topk_kernel(float* __restrict__ out) {
    extern __shared__ unsigned long long key[];
    const int e = blockIdx.x;
    const int tid = threadIdx.x;

    for (int i = tid; i < NT; i += 1024) {
        const unsigned b = __float_as_uint(g_logits[i * NEXP + e]);
        const unsigned m = b ^ ((b & 0x80000000u) ? 0xFFFFFFFFu : 0x80000000u);
        key[i] = ((unsigned long long)(~m) << 32) | (unsigned)i;
    }
    __syncthreads();

    for (unsigned k = 2; k <= NT; k <<= 1) {
        for (unsigned j = k >> 1; j > 0; j >>= 1) {
            for (unsigned i = tid; i < NT; i += 1024) {
                const unsigned ixj = i ^ j;
                if (ixj > i) {
                    const bool up = ((i & k) == 0);
                    const unsigned long long a = key[i], b = key[ixj];
                    if ((a > b) == up) { key[i] = b; key[ixj] = a; }
                }
            }
            __syncthreads();
        }
    }

    if (tid < KSEL) {
        const unsigned long long kk = key[tid];
        const unsigned idx = (unsigned)(kk & 0xFFFFFFFFu);
        const unsigned m = ~((unsigned)(kk >> 32));
        const unsigned b = (m & 0x80000000u) ? (m ^ 0x80000000u) : ~m;
        const float val = __uint_as_float(b);

        out[OFF_IDX + e * KSEL + tid] = (float)idx;
        out[OFF_W   + e * KSEL + tid] = g_weights[idx * NEXP + e];
        g_selidx[e * KSEL + tid] = (int)idx;
        atomicAdd(&out[OFF_FAN + idx], 1.0f);
        if (tid == KSEL - 1) out[OFF_CUT + e] = val;
    }
}

// ---------------- kernel 3: fp32 -> bf16 hi/lo split -----------------------
extern "C" __global__ void split_kernel(const float* __restrict__ in,
                                        __nv_bfloat16* __restrict__ hi,
                                        __nv_bfloat16* __restrict__ lo, int n4) {
    const int i = blockIdx.x * blockDim.x + threadIdx.x;
    if (i >= n4) return;
    const float4 v = ((const float4*)in)[i];
    union { __nv_bfloat16 b[4]; uint2 u; } ph, pl;
    float vv[4] = {v.x, v.y, v.z, v.w};
#pragma unroll
    for (int j = 0; j < 4; j++) {
        __nv_bfloat16 h = __float2bfloat16(vv[j]);
        ph.b[j] = h;
        pl.b[j] = __float2bfloat16(vv[j] - __bfloat162float(h));
    }
    ((uint2*)hi)[i] = ph.u;
    ((uint2*)lo)[i] = pl.u;
}

// ---------------- kernels 4/5: mma.sync bf16x3 GEMM ------------------------
// Round-13: 3-stage cp.async pipeline, ONE __syncthreads per chunk.
// Same tile/layout as the measured round-10/12 config: CTA 128x128, 8 warps
// of 32(m)x64(n), k-chunk 32, ROWB=80.
#define ROWB 80
#define OPER_B (128 * ROWB)          // 10240 per operand per stage
#define STG_B  (2 * OPER_B)          // 20480 per stage
#define SMEM_MMA (3 * STG_B + 512)   // 3 stages + sidx

template <int KREAL, int NDIM, int GATHER, int RELU2OUT>
__global__ void __launch_bounds__(256, 2)
mma_gemm(const __nv_bfloat16* __restrict__ Ahi, const __nv_bfloat16* __restrict__ Alo,
         const __nv_bfloat16* __restrict__ Bhi, const __nv_bfloat16* __restrict__ Blo,
         float* __restrict__ Cf,
         __nv_bfloat16* __restrict__ Chi, __nv_bfloat16* __restrict__ Clo) {
    extern __shared__ char smem[];
    const uint32_t sb = smem_u32(smem);
    const int tid = threadIdx.x, wid = tid >> 5, lane = tid & 31;
    const int m0 = blockIdx.x * 128, n0 = blockIdx.y * 128, e = blockIdx.z;

    int* sidx = (int*)(smem + 3 * STG_B);
    if (GATHER && tid < 128) sidx[tid] = g_selidx[e * KSEL + m0 + tid];
    __syncthreads();

    const int r0 = tid >> 2, sg = tid & 3, r1 = r0 + 64;
    const size_t ar0 = GATHER ? (size_t)sidx[r0] : ((size_t)e * 1024 + m0 + r0);
    const size_t ar1 = GATHER ? (size_t)sidx[r1] : ((size_t)e * 1024 + m0 + r1);
    const size_t br0 = (size_t)e * NDIM + n0 + r0;
    const size_t br1 = (size_t)e * NDIM + n0 + r1;
    const uint32_t aoff0 = r0 * ROWB + sg * 16;
    const uint32_t aoff1 = r1 * ROWB + sg * 16;

    constexpr int KC = KREAL / 32;
    constexpr int NCH = 3 * KC;

    auto issue = [&](int c, int st) {
        const int b = c / KC;
        const int kk = (c - b * KC) * 32;
        const __nv_bfloat16* Ap = (b == 2) ? Alo : Ahi;
        const __nv_bfloat16* Bp = (b == 1) ? Blo : Bhi;
        const uint32_t base = sb + st * STG_B;
        CP_ASYNC16(base + aoff0, Ap + ar0 * KREAL + kk + sg * 8);
        CP_ASYNC16(base + aoff1, Ap + ar1 * KREAL + kk + sg * 8);
        CP_ASYNC16(base + OPER_B + aoff0, Bp + br0 * KREAL + kk + sg * 8);
        CP_ASYNC16(base + OPER_B + aoff1, Bp + br1 * KREAL + kk + sg * 8);
        CP_COMMIT();
    };

    // warp tile: 32(m) x 64(n)
    const int wm = wid & 3, wn = wid >> 2;
    const uint32_t a_l = (uint32_t)(wm * 32 + (lane & 15)) * ROWB + (lane >> 4) * 16;
    const uint32_t b_l = (uint32_t)(wn * 64 + (lane & 7) + ((lane >> 4) & 1) * 8) * ROWB
                         + ((lane >> 3) & 1) * 16;

    float d[2][8][4] = {};

    issue(0, 0);
    issue(1, 1);
    for (int c = 0; c < NCH; c++) {
        const int st = c % 3;
        if (c + 1 < NCH) CP_WAIT1(); else CP_WAIT0();
        __syncthreads();
        // safe: barrier above guarantees all warps finished reading stage
        // (c+2)%3 == (c-1)%3 during chunk c-1.
        if (c + 2 < NCH) issue(c + 2, (c + 2) % 3);

        const uint32_t ab = sb + st * STG_B;
        const uint32_t bb = ab + OPER_B;
#pragma unroll
        for (int ks = 0; ks < 2; ks++) {
            uint32_t a[2][4], bf[8][2];
#pragma unroll
            for (int mi = 0; mi < 2; mi++)
                ldsm4(a[mi][0], a[mi][1], a[mi][2], a[mi][3],
                      ab + a_l + mi * 16 * ROWB + ks * 32);
#pragma unroll
            for (int nb = 0; nb < 4; nb++) {
                uint32_t t0, t1, t2, t3;
                ldsm4(t0, t1, t2, t3, bb + b_l + nb * 16 * ROWB + ks * 32);
                bf[2 * nb][0] = t0; bf[2 * nb][1] = t1;
                bf[2 * nb + 1][0] = t2; bf[2 * nb + 1][1] = t3;
            }
#pragma unroll
            for (int mi = 0; mi < 2; mi++)
#pragma unroll
                for (int ni = 0; ni < 8; ni++)
                    mma16816(d[mi][ni], a[mi], bf[ni]);
        }
    }

    // epilogue
    const int mb = m0 + wm * 32;
    const int nb0 = n0 + wn * 64;
#pragma unroll
    for (int mi = 0; mi < 2; mi++)
#pragma unroll
        for (int half = 0; half < 2; half++) {
            const int m = mb + mi * 16 + (lane >> 2) + half * 8;
            const size_t rowoff = ((size_t)e * 1024 + m) * NDIM;
#pragma unroll
            for (int ni = 0; ni < 8; ni++) {
                const int n = nb0 + ni * 8 + (lane & 3) * 2;
                float v0 = d[mi][ni][2 * half + 0];
                float v1 = d[mi][ni][2 * half + 1];
                if (RELU2OUT) {
                    v0 = fmaxf(v0, 0.0f); v0 *= v0;
                    v1 = fmaxf(v1, 0.0f); v1 *= v1;
                    __nv_bfloat16 h0 = __float2bfloat16(v0);
                    __nv_bfloat16 h1 = __float2bfloat16(v1);
                    __nv_bfloat16 l0 = __float2bfloat16(v0 - __bfloat162float(h0));
                    __nv_bfloat16 l1 = __float2bfloat16(v1 - __bfloat162float(h1));
                    __nv_bfloat162 hp; hp.x = h0; hp.y = h1;
                    __nv_bfloat162 lp; lp.x = l0; lp.y = l1;
                    *(__nv_bfloat162*)(Chi + rowoff + n) = hp;
                    *(__nv_bfloat162*)(Clo + rowoff + n) = lp;
                } else {
                    float2 s2; s2.x = v0; s2.y = v1;
                    *(float2*)(Cf + rowoff + n) = s2;
                }
            }
        }
}

// ---------------- launch ----------------
extern "C" void kernel_launch(void* const* d_in, const int* in_sizes, int n_in,
                              void* d_out, int out_size) {
    const float* x  = (const float*)d_in[0];
    const float* rw = (const float*)d_in[1];
    const float* w1 = (const float*)d_in[2];
    const float* w2 = (const float*)d_in[3];
    float* out = (float*)d_out;

    cudaFuncSetAttribute(router_seq_kernel,
                         cudaFuncAttributeMaxDynamicSharedMemorySize, 101376);
    cudaFuncSetAttribute(topk_kernel,
                         cudaFuncAttributeMaxDynamicSharedMemorySize, 65536);
    cudaFuncSetAttribute(mma_gemm<NE, ED, 1, 1>,
                         cudaFuncAttributeMaxDynamicSharedMemorySize, SMEM_MMA);
    cudaFuncSetAttribute(mma_gemm<ED, NE, 0, 0>,
                         cudaFuncAttributeMaxDynamicSharedMemorySize, SMEM_MMA);

    __nv_bfloat16 *xhi, *xlo, *w1hi, *w1lo, *w2hi, *w2lo, *hhi, *hlo;
    cudaGetSymbolAddress((void**)&xhi,  g_xhi);
    cudaGetSymbolAddress((void**)&xlo,  g_xlo);
    cudaGetSymbolAddress((void**)&w1hi, g_w1hi);
    cudaGetSymbolAddress((void**)&w1lo, g_w1lo);
    cudaGetSymbolAddress((void**)&w2hi, g_w2hi);
    cudaGetSymbolAddress((void**)&w2lo, g_w2lo);
    cudaGetSymbolAddress((void**)&hhi,  g_hhi);
    cudaGetSymbolAddress((void**)&hlo,  g_hlo);

    // 1) bf16 hi/lo splits
    split_kernel<<<(NT * NE / 4 + 255) / 256, 256>>>(x, xhi, xlo, NT * NE / 4);
    split_kernel<<<(NEXP * ED * NE / 4 + 255) / 256, 256>>>(w1, w1hi, w1lo, NEXP * ED * NE / 4);
    split_kernel<<<(NEXP * NE * ED / 4 + 255) / 256, 256>>>(w2, w2hi, w2lo, NEXP * NE * ED / 4);

    // 2) router logits (EXACT reference fp32 order) + softmax + fanout zero
    router_seq_kernel<<<NT / 8, 128, ROUTER_SMEM>>>(x, rw, out);

    // 3) exact top-1024 per expert
    topk_kernel<<<NEXP, 1024, 65536>>>(out);

    // 4) h = relu(x_sel @ w1^T)^2 -> bf16 hi/lo planes (mma.sync bf16x3)
    {
        dim3 grid(KSEL / 128, ED / 128, NEXP);
        mma_gemm<NE, ED, 1, 1><<<grid, 256, SMEM_MMA>>>(
            xhi, xlo, w1hi, w1lo, nullptr, hhi, hlo);
    }
    // 5) h_flat = h @ w2^T -> d_out (mma.sync bf16x3)
    {
        dim3 grid(KSEL / 128, NE / 128, NEXP);
        mma_gemm<ED, NE, 0, 0><<<grid, 256, SMEM_MMA>>>(
            hhi, hlo, w2hi, w2lo, out + OFF_H, nullptr, nullptr);
    }
}